// round 6
// baseline (speedup 1.0000x reference)
#include <cuda_runtime.h>
#include <math.h>

#define Bq 4
#define Lq 4096
#define Hq 8
#define Dq 64
#define SK 9
#define U  9
#define BH (Bq*Hq)
#define NCH 8
#define CHK (Lq/NCH)   // 512
#define NSAMP_BLOCKS ((BH*Lq)/8)   // 16384 (8 warps/block)

// scratch (static __device__ arrays — no allocation)
__device__ float  g_M[BH * Lq];
__device__ int    g_top[BH * U];
__device__ float4 g_vmean4[BH * (Dq/4)];
__device__ float  g_vpart[BH * NCH * Dq];
__device__ float  g_cand_v[BH * NCH * U];
__device__ int    g_cand_i[BH * NCH * U];
__device__ int    g_cnt[BH];
__device__ float  g_scores[BH * U * Lq];        // raw scores, then normalized attn

// ---------------------------------------------------------------------------
// L1: sample scores (blocks 0..16383) || V-mean partials (blocks 16384..16639)
// ---------------------------------------------------------------------------
__global__ void __launch_bounds__(256)
k_setup(const float* __restrict__ q,
        const float* __restrict__ k,
        const float* __restrict__ v,
        const int*   __restrict__ idx)
{
    if (blockIdx.x >= NSAMP_BLOCKS) {
        // ---- V mean partial ----
        int blk = blockIdx.x - NSAMP_BLOCKS;          // 0..255
        int bh = blk >> 3, ch = blk & 7;
        int b = bh / Hq, h = bh % Hq;
        int t = threadIdx.x;
        if (ch == 0 && t == 0) g_cnt[bh] = 0;         // reset merge counter (used next launch)
        int d = t & 63, g = t >> 6;                   // 4 l-groups x 64 d
        float acc = 0.f;
        int lend = (ch + 1) * CHK;
        for (int l = ch * CHK + g; l < lend; l += 4)
            acc += v[((size_t)(b * Lq + l) * Hq + h) * Dq + d];
        __shared__ float red[256];
        red[t] = acc;
        __syncthreads();
        if (t < 128) red[t] += red[t + 128];
        __syncthreads();
        if (t < 64) g_vpart[(bh * NCH + ch) * Dq + t] = red[t] + red[t + 64];
        return;
    }

    // ---- sampled scores: one warp per (b,h,l), half-warp per sample ----
    int warp = (blockIdx.x * 256 + threadIdx.x) >> 5;
    int lane = threadIdx.x & 31;
    int l  = warp % Lq;
    int bh = warp / Lq;
    int b = bh / Hq, h = bh % Hq;

    const float4* qrow = (const float4*)(q + ((size_t)(b * Lq + l) * Hq + h) * Dq);
    float4 q4 = qrow[lane & 15];
    int half = lane >> 4;                 // 0 or 1

    // load all 5 sample indices for this half, then issue all gathers (MLP=5)
    int ks[5];
#pragma unroll
    for (int j = 0; j < 5; j++) {
        int s2 = 2 * j + half;
        if (s2 >= SK) s2 = SK - 1;
        ks[j] = idx[l * SK + s2];
    }
    float4 kv[5];
#pragma unroll
    for (int j = 0; j < 5; j++)
        kv[j] = ((const float4*)(k + ((size_t)(b * Lq + ks[j]) * Hq + h) * Dq))[lane & 15];

    float mx = -INFINITY, sm = 0.f;
#pragma unroll
    for (int j = 0; j < 5; j++) {
        float p = kv[j].x * q4.x + kv[j].y * q4.y + kv[j].z * q4.z + kv[j].w * q4.w;
        p += __shfl_xor_sync(0xffffffffu, p, 1);
        p += __shfl_xor_sync(0xffffffffu, p, 2);
        p += __shfl_xor_sync(0xffffffffu, p, 4);
        p += __shfl_xor_sync(0xffffffffu, p, 8);
        float p0 = __shfl_sync(0xffffffffu, p, 0);
        float p1 = __shfl_sync(0xffffffffu, p, 16);
        mx = fmaxf(mx, p0); sm += p0;
        if (2 * j + 1 < SK) { mx = fmaxf(mx, p1); sm += p1; }
    }
    if (lane == 0) g_M[bh * Lq + l] = mx - sm * (1.0f / (float)Lq);
}

// ---------------------------------------------------------------------------
// L2: per-chunk top-9; the LAST finishing block of each bh merges the 72
// candidates into g_top and finishes the V mean. grid = bh*NCH, 128 threads
// ---------------------------------------------------------------------------
__global__ void __launch_bounds__(128)
k_topk()
{
    int blk = blockIdx.x;
    int bh = blk >> 3, ch = blk & 7;
    int base = ch * CHK;
    int t = threadIdx.x;

    __shared__ float sv[CHK];
    __shared__ float rv[128];
    __shared__ int   ri[128];

    for (int i = t; i < CHK; i += 128) sv[i] = g_M[bh * Lq + base + i];
    __syncthreads();

    for (int r = 0; r < U; r++) {
        float bv = -INFINITY; int bi = 0x7fffffff;
#pragma unroll
        for (int j = 0; j < CHK / 128; j++) {
            int i = t + j * 128;
            float vv = sv[i];
            if (vv > bv || (vv == bv && i < bi)) { bv = vv; bi = i; }
        }
        rv[t] = bv; ri[t] = bi;
        __syncthreads();
        for (int o = 64; o > 0; o >>= 1) {
            if (t < o) {
                float v2 = rv[t + o]; int i2 = ri[t + o];
                if (v2 > rv[t] || (v2 == rv[t] && i2 < ri[t])) { rv[t] = v2; ri[t] = i2; }
            }
            __syncthreads();
        }
        if (t == 0) {
            g_cand_v[blk * U + r] = rv[0];
            g_cand_i[blk * U + r] = base + ri[0];
            sv[ri[0]] = -INFINITY;
        }
        __syncthreads();
    }

    // last block of this bh does the merge + vmean finish
    __threadfence();
    __shared__ int is_last;
    if (t == 0) is_last = (atomicAdd(&g_cnt[bh], 1) == NCH - 1);
    __syncthreads();
    if (!is_last) return;

    if (t >= 32 && t < 96) {
        int d = t - 32;
        float s = 0.f;
#pragma unroll
        for (int c = 0; c < NCH; c++) s += g_vpart[(bh * NCH + c) * Dq + d];
        ((float*)g_vmean4)[bh * Dq + d] = s * (1.0f / (float)Lq);
    }

    if (t < 32) {
        const int NC = NCH * U;          // 72
        float v0 = -INFINITY, v1 = -INFINITY, v2 = -INFINITY;
        int   i0 = 0x7fffffff, i1 = 0x7fffffff, i2 = 0x7fffffff;
        if (t      < NC) { v0 = g_cand_v[bh * NC + t];      i0 = g_cand_i[bh * NC + t]; }
        if (t + 32 < NC) { v1 = g_cand_v[bh * NC + t + 32]; i1 = g_cand_i[bh * NC + t + 32]; }
        if (t + 64 < NC) { v2 = g_cand_v[bh * NC + t + 64]; i2 = g_cand_i[bh * NC + t + 64]; }

        for (int r = 0; r < U; r++) {
            float bv = v0; int bi = i0;
            if (v1 > bv || (v1 == bv && i1 < bi)) { bv = v1; bi = i1; }
            if (v2 > bv || (v2 == bv && i2 < bi)) { bv = v2; bi = i2; }
#pragma unroll
            for (int o = 16; o > 0; o >>= 1) {
                float ov = __shfl_xor_sync(0xffffffffu, bv, o);
                int   oi = __shfl_xor_sync(0xffffffffu, bi, o);
                if (ov > bv || (ov == bv && oi < bi)) { bv = ov; bi = oi; }
            }
            if (t == 0) g_top[bh * U + r] = bi;
            if (i0 == bi) v0 = -INFINITY;
            if (i1 == bi) v1 = -INFINITY;
            if (i2 == bi) v2 = -INFINITY;
        }
    }
}

// ---------------------------------------------------------------------------
// L3: raw scores (blocks 0..255) || bcast vmean w/ zeroed top rows (rest)
// ---------------------------------------------------------------------------
#define NBCAST ((Bq*Lq*Hq*Dq/4)/256)   // 8192

__global__ void __launch_bounds__(256)
k_mid(const float* __restrict__ q, const float* __restrict__ k,
      float4* __restrict__ out4)
{
    int t = threadIdx.x;
    if (blockIdx.x >= 256) {
        // ---- broadcast: out[b,l,h,:] = vmean[b,h] unless l in top(b,h) -> 0
        int f = (blockIdx.x - 256) * 256 + t;
        int b = f >> 19;
        int h = (f >> 4) & 7;
        int l = (f >> 7) & 4095;
        int bh = b * Hq + h;
        bool hit = false;
#pragma unroll
        for (int r = 0; r < U; r++) hit |= (g_top[bh * U + r] == l);
        float4 z = make_float4(0.f, 0.f, 0.f, 0.f);
        out4[f] = hit ? z : g_vmean4[(bh << 4) + (f & 15)];
        return;
    }

    // ---- scores for top-u queries; chunked over K
    int blk = blockIdx.x;
    int bh = blk >> 3, ch = blk & 7;
    int b = bh / Hq, h = bh % Hq;

    __shared__ float qr[U * Dq];
    for (int i = t; i < U * Dq; i += 256) {
        int r = i >> 6, d = i & 63;
        int l = g_top[bh * U + r];
        qr[i] = q[((size_t)(b * Lq + l) * Hq + h) * Dq + d];
    }
    __syncthreads();

    const float scale = 0.125f;
    int kend = (ch + 1) * CHK;
    for (int kk = ch * CHK + t; kk < kend; kk += 256) {
        const float4* krow = (const float4*)(k + ((size_t)(b * Lq + kk) * Hq + h) * Dq);
        float dot[U];
#pragma unroll
        for (int r = 0; r < U; r++) dot[r] = 0.f;
#pragma unroll
        for (int i = 0; i < Dq / 4; i++) {
            float4 kv = krow[i];
#pragma unroll
            for (int r = 0; r < U; r++) {
                dot[r] += kv.x * qr[r * Dq + 4 * i + 0]
                        + kv.y * qr[r * Dq + 4 * i + 1]
                        + kv.z * qr[r * Dq + 4 * i + 2]
                        + kv.w * qr[r * Dq + 4 * i + 3];
            }
        }
#pragma unroll
        for (int r = 0; r < U; r++) g_scores[((size_t)(bh * U + r)) * Lq + kk] = dot[r] * scale;
    }
}

// ---------------------------------------------------------------------------
// L4: softmax per row + attn output write; grid = bh*U, 512 threads
// ---------------------------------------------------------------------------
__global__ void __launch_bounds__(512)
k_softmax(float* __restrict__ out)
{
    int blk = blockIdx.x;                 // = bh*U + r, matches attn layout (b,h,u,l)
    float* row = g_scores + (size_t)blk * Lq;
    __shared__ float sr[Lq];
    __shared__ float red[512];
    int t = threadIdx.x;

    float mx = -INFINITY;
    for (int kk = t; kk < Lq; kk += 512) {
        float s = row[kk];
        sr[kk] = s;
        mx = fmaxf(mx, s);
    }
    red[t] = mx; __syncthreads();
    for (int o = 256; o > 0; o >>= 1) {
        if (t < o) red[t] = fmaxf(red[t], red[t + o]);
        __syncthreads();
    }
    mx = red[0]; __syncthreads();

    float sm = 0.f;
    for (int kk = t; kk < Lq; kk += 512) {
        float e = expf(sr[kk] - mx);
        sr[kk] = e;
        sm += e;
    }
    red[t] = sm; __syncthreads();
    for (int o = 256; o > 0; o >>= 1) {
        if (t < o) red[t] += red[t + o];
        __syncthreads();
    }
    float inv = 1.0f / red[0];

    float* attn = out + (size_t)Bq * Lq * Hq * Dq + (size_t)blk * Lq;
    for (int kk = t; kk < Lq; kk += 512) {
        float a = sr[kk] * inv;
        row[kk] = a;
        attn[kk] = a;
    }
}

// ---------------------------------------------------------------------------
// L5: ctx partials, atomically accumulated into the (pre-zeroed) top rows
// grid = bh*NCH, 512 threads
// ---------------------------------------------------------------------------
__global__ void __launch_bounds__(512)
k_ctx(const float* __restrict__ v, float* __restrict__ out)
{
    int blk = blockIdx.x;
    int bh = blk >> 3, ch = blk & 7;
    int b = bh / Hq, h = bh % Hq;
    int t = threadIdx.x;
    int d = t & 63, g = t >> 6;           // 8 k-groups x 64 d

    const float* sc = g_scores + (size_t)bh * U * Lq;
    float acc[U];
#pragma unroll
    for (int r = 0; r < U; r++) acc[r] = 0.f;

    int kend = (ch + 1) * CHK;
    for (int kk = ch * CHK + g; kk < kend; kk += 8) {
        float vv = v[((size_t)(b * Lq + kk) * Hq + h) * Dq + d];
#pragma unroll
        for (int r = 0; r < U; r++) acc[r] += sc[r * Lq + kk] * vv;
    }

    __shared__ float cred[8 * U * Dq];
#pragma unroll
    for (int r = 0; r < U; r++) cred[((g * U + r) << 6) + d] = acc[r];
    __syncthreads();

    for (int i = t; i < U * Dq; i += 512) {
        int r = i >> 6, dd = i & 63;
        float s = 0.f;
#pragma unroll
        for (int gg = 0; gg < 8; gg++) s += cred[((gg * U + r) << 6) + dd];
        int l = g_top[bh * U + r];
        atomicAdd(&out[((size_t)(b * Lq + l) * Hq + h) * Dq + dd], s);
    }
}

// ---------------------------------------------------------------------------
extern "C" void kernel_launch(void* const* d_in, const int* in_sizes, int n_in,
                              void* d_out, int out_size)
{
    const float* q   = (const float*)d_in[0];
    const float* k   = (const float*)d_in[1];
    const float* v   = (const float*)d_in[2];
    const int*   idx = (const int*)d_in[3];
    float* out = (float*)d_out;

    (void)in_sizes; (void)n_in; (void)out_size;

    k_setup<<<NSAMP_BLOCKS + BH * NCH, 256>>>(q, k, v, idx);
    k_topk<<<BH * NCH, 128>>>();
    k_mid<<<256 + NBCAST, 256>>>(q, k, (float4*)out);
    k_softmax<<<BH * U, 512>>>(out);
    k_ctx<<<BH * NCH, 512>>>(v, out);
}